// round 10
// baseline (speedup 1.0000x reference)
#include <cuda_runtime.h>
#include <cstdint>

#define NSEG 100000
#define CAP  128            // Poisson(42): P(>=128) ~ 1e-26/seg; pow2 => aligned buckets

// static scratch (no cudaMalloc allowed). Zero at module load; kernel restores
// all state to zero before exit so every graph replay starts clean.
__device__ unsigned g_arrive = 0;
__device__ unsigned g_done   = 0;
__device__ int g_cnt[NSEG];
__device__ int g_rowid[NSEG * CAP];   // 51.2 MB bucket array

__global__ void __launch_bounds__(256, 6)
fused_kernel(const float4* __restrict__ x,
             const int2*  __restrict__ idx2,
             int n2, int n_rows,
             float* __restrict__ out) {
    const int tid      = blockIdx.x * blockDim.x + threadIdx.x;
    const int nthreads = gridDim.x * blockDim.x;

    // ---- phase 1: bucket row ids by segment (grid-stride, int2 per step) ----
    for (int t = tid; t < n2; t += nthreads) {
        int2 v = __ldcs(&idx2[t]);                 // touch-once: evict-first
        int base = t * 2;
        int p0 = atomicAdd(&g_cnt[v.x], 1);
        int p1 = atomicAdd(&g_cnt[v.y], 1);
        __stcs(&g_rowid[v.x * CAP + p0], base);    // read-once by phase 2
        __stcs(&g_rowid[v.y * CAP + p1], base + 1);
    }
    if (tid == 0 && (n_rows & 1)) {                // odd-row tail (robustness)
        int seg = __ldg(&((const int*)idx2)[n_rows - 1]);
        int pos = atomicAdd(&g_cnt[seg], 1);
        g_rowid[seg * CAP + pos] = n_rows - 1;
    }

    // ---- gridwide barrier (all CTAs co-resident via launch_bounds) ----
    __syncthreads();
    if (threadIdx.x == 0) {
        __threadfence();                           // publish phase-1 stores
        atomicAdd(&g_arrive, 1u);
        while (atomicAdd(&g_arrive, 0u) < gridDim.x) __nanosleep(64);
    }
    __syncthreads();

    // ---- phase 2: gather-reduce, one warp per segment (grid-stride) ----
    const int warp   = tid >> 5;
    const int lane   = threadIdx.x & 31;
    const int nwarps = nthreads >> 5;
    const int half   = lane >> 4;     // which row of the pair
    const int q      = lane & 15;     // which float4 of the row

    for (int s = warp; s < NSEG; s += nwarps) {
        int cnt = __ldcg(&g_cnt[s]);               // L2-fresh
        int m   = min(cnt, CAP);
        const int* __restrict__ bucket = &g_rowid[s * CAP];

        float4 acc = make_float4(0.f, 0.f, 0.f, 0.f);
        #pragma unroll 4
        for (int j = half; j < m; j += 2) {
            int row = __ldg(&bucket[j]);                    // broadcast / 16 lanes
            float4 v = __ldcs(&x[(long long)row * 16 + q]); // touch-once
            acc.x += v.x; acc.y += v.y; acc.z += v.z; acc.w += v.w;
        }

        acc.x += __shfl_down_sync(0xffffffffu, acc.x, 16);
        acc.y += __shfl_down_sync(0xffffffffu, acc.y, 16);
        acc.z += __shfl_down_sync(0xffffffffu, acc.z, 16);
        acc.w += __shfl_down_sync(0xffffffffu, acc.w, 16);

        if (lane < 16) {
            float inv = 1.0f / fmaxf((float)cnt, 1.0f);
            float4 r = make_float4(acc.x * inv, acc.y * inv,
                                   acc.z * inv, acc.w * inv);
            __stcs(&((float4*)out)[(long long)s * 16 + q], r);
        }
        if (lane == 0) g_cnt[s] = 0;               // reset for next replay
    }

    // ---- exit protocol: last CTA resets the barrier counters ----
    __syncthreads();
    if (threadIdx.x == 0) {
        unsigned old = atomicAdd(&g_done, 1u);
        if (old == gridDim.x - 1u) {
            atomicExch(&g_arrive, 0u);
            atomicExch(&g_done, 0u);
        }
    }
}

extern "C" void kernel_launch(void* const* d_in, const int* in_sizes, int n_in,
                              void* d_out, int out_size) {
    const float4* x    = (const float4*)d_in[0];
    const int2*   idx2 = (const int2*)d_in[1];
    float* out = (float*)d_out;

    int n_rows = in_sizes[1];          // 4194304
    int n2 = n_rows / 2;

    int dev = 0, sms = 148;
    cudaGetDevice(&dev);
    cudaDeviceGetAttribute(&sms, cudaDevAttrMultiProcessorCount, dev);

    int blocks = sms * 6;              // co-resident by __launch_bounds__(256,6)
    fused_kernel<<<blocks, 256>>>(x, idx2, n2, n_rows, out);
}

// round 11
// speedup vs baseline: 1.0116x; 1.0116x over previous
#include <cuda_runtime.h>
#include <cstdint>

#define NSEG 100000
#define CAP  64             // buckets = 25.6 MB -> L2-resident. Poisson(42):
                            // P(>64) ~ 3e-4/seg; spill handled by overflow list.
#define MAXOVER 32768       // overflow capacity (expected ~50 entries)

// static scratch (no cudaMalloc allowed). Zero at module load; kernels restore
// all state to zero before the next replay.
__device__ int   g_cnt[NSEG];
__device__ float g_cntf[NSEG];          // count snapshot for overflow divide
__device__ int   g_rowid[NSEG * CAP];   // 25.6 MB bucket array (L2-resident)
__device__ int   g_overcnt;
__device__ int2  g_over[MAXOVER];       // (seg, row) spill entries

// one thread per 2 rows: read int2 of index, bump cursor, drop row-id in bucket
// (or overflow list if the bucket is full).
__global__ void build_buckets_kernel(const int2* __restrict__ idx2, int n2) {
    int t = blockIdx.x * blockDim.x + threadIdx.x;
    if (t >= n2) return;
    int2 v = __ldcs(&idx2[t]);                 // touch-once: evict-first
    int base = t * 2;
    int p0 = atomicAdd(&g_cnt[v.x], 1);
    int p1 = atomicAdd(&g_cnt[v.y], 1);
    if (p0 < CAP) {
        g_rowid[v.x * CAP + p0] = base;        // default store: keep in L2
    } else {
        int o = atomicAdd(&g_overcnt, 1);
        if (o < MAXOVER) g_over[o] = make_int2(v.x, base);
    }
    if (p1 < CAP) {
        g_rowid[v.y * CAP + p1] = base + 1;
    } else {
        int o = atomicAdd(&g_overcnt, 1);
        if (o < MAXOVER) g_over[o] = make_int2(v.y, base + 1);
    }
}

// one warp per segment; lanes 0-15 handle row j, lanes 16-31 handle row j+1.
// Each lane accumulates one float4 of the 256B row; shfl combine; lanes 0-15
// write mean of bucketed rows (divided by FULL count). Snapshots count, resets cursor.
__global__ void gather_kernel(const float4* __restrict__ x,
                              float* __restrict__ out) {
    int warp = (blockIdx.x * blockDim.x + threadIdx.x) >> 5;
    int lane = threadIdx.x & 31;
    if (warp >= NSEG) return;

    int s    = warp;
    int cnt  = g_cnt[s];
    int m    = min(cnt, CAP);
    int half = lane >> 4;
    int q    = lane & 15;

    const int* __restrict__ bucket = &g_rowid[s * CAP];

    float4 acc = make_float4(0.f, 0.f, 0.f, 0.f);

    #pragma unroll 4
    for (int j = half; j < m; j += 2) {
        int row = __ldg(&bucket[j]);                        // L2 hit (resident)
        float4 v = __ldcs(&x[(long long)row * 16 + q]);     // touch-once stream
        acc.x += v.x; acc.y += v.y; acc.z += v.z; acc.w += v.w;
    }

    acc.x += __shfl_down_sync(0xffffffffu, acc.x, 16);
    acc.y += __shfl_down_sync(0xffffffffu, acc.y, 16);
    acc.z += __shfl_down_sync(0xffffffffu, acc.z, 16);
    acc.w += __shfl_down_sync(0xffffffffu, acc.w, 16);

    if (lane < 16) {
        float inv = 1.0f / fmaxf((float)cnt, 1.0f);         // FULL count
        float4 r = make_float4(acc.x * inv, acc.y * inv, acc.z * inv, acc.w * inv);
        __stcs(&((float4*)out)[(long long)s * 16 + q], r);
    }

    if (lane == 0) {
        g_cntf[s] = (float)cnt;    // snapshot for overflow kernel
        g_cnt[s]  = 0;             // reset cursor for next replay
    }
}

// single CTA: add spilled rows (x[row]/cnt[seg]) into out, then reset overflow
// cursor. Runs after gather (stream order makes gather's writes visible).
__global__ void overflow_kernel(const float4* __restrict__ x,
                                float* __restrict__ out) {
    int n = g_overcnt;
    if (n > MAXOVER) n = MAXOVER;
    for (int j = threadIdx.x; j < n; j += blockDim.x) {
        int2 e = g_over[j];
        float inv = 1.0f / fmaxf(g_cntf[e.x], 1.0f);
        const float4* xr = &x[(long long)e.y * 16];
        float* dst = out + (long long)e.x * 64;
        #pragma unroll
        for (int q = 0; q < 16; q++) {
            float4 v = __ldg(&xr[q]);
            asm volatile("red.global.add.v4.f32 [%0], {%1,%2,%3,%4};"
                         :: "l"(dst + q * 4),
                            "f"(v.x * inv), "f"(v.y * inv),
                            "f"(v.z * inv), "f"(v.w * inv)
                         : "memory");
        }
    }
    __syncthreads();
    if (threadIdx.x == 0) g_overcnt = 0;
}

extern "C" void kernel_launch(void* const* d_in, const int* in_sizes, int n_in,
                              void* d_out, int out_size) {
    const float4* x    = (const float4*)d_in[0];
    const int2*   idx2 = (const int2*)d_in[1];
    float* out = (float*)d_out;

    int n_rows = in_sizes[1];          // 4194304
    int n2 = n_rows / 2;

    // 1) bucket row ids by segment
    build_buckets_kernel<<<(n2 + 255) / 256, 256>>>(idx2, n2);

    // 2) gather-reduce: one warp per segment, writes means directly
    {
        long long total_threads = (long long)NSEG * 32;
        int threads = 256;
        int blocks = (int)((total_threads + threads - 1) / threads);
        gather_kernel<<<blocks, threads>>>(x, out);
    }

    // 3) fold in overflow rows (rare) + reset overflow cursor
    overflow_kernel<<<1, 256>>>(x, out);
}